// round 4
// baseline (speedup 1.0000x reference)
#include <cuda_runtime.h>
#include <cstdint>

// Problem constants (ClassicMambaBlock: B=2, L=2048, Dm=1024, E=2048, N=16, R=64, K=3)
static constexpr int BSZ  = 2;
static constexpr int LEN  = 2048;
static constexpr int DM   = 1024;
static constexpr int EE   = 2048;
static constexpr int NN   = 16;
static constexpr int RR   = 64;
static constexpr int SEL  = RR + 2 * NN;   // 96
static constexpr int MTOT = BSZ * LEN;     // 4096

// ---------------- scratch (no cudaMalloc allowed) ----------------
__device__ float g_xz[MTOT * 2 * EE];     // [M, 4096] : cols [0,E)=xc, [E,2E)=z
__device__ float g_u[MTOT * EE];          // conv+silu output (full precision, for scan)
__device__ float g_ur[MTOT * EE];         // conv+silu output rounded to tf32 (for GEMM3)
__device__ float g_dbc[MTOT * SEL];       // [M, 96]: dt_low(tf32-rounded) | B | C
__device__ float g_delta[MTOT * EE];      // softplus(dt)
__device__ float g_y[MTOT * EE];          // gated scan output (tf32-rounded, feeds GEMM6)
// tf32-pre-rounded operand copies
__device__ float g_xr[MTOT * DM];
__device__ float g_winr[2 * EE * DM];
__device__ float g_wselr[SEL * EE];
__device__ float g_dtwr[EE * RR];
__device__ float g_woutr[DM * EE];

// ================= helpers =================
__device__ __forceinline__ uint32_t smem_u32(const void* p) {
    uint32_t a;
    asm("{ .reg .u64 t; cvta.to.shared.u64 t, %1; cvt.u32.u64 %0, t; }" : "=r"(a) : "l"(p));
    return a;
}
__device__ __forceinline__ void cp_async16(uint32_t dst, const void* src) {
    asm volatile("cp.async.cg.shared.global [%0], [%1], 16;" :: "r"(dst), "l"(src));
}
__device__ __forceinline__ float f2tf32(float f) {
    uint32_t u;
    asm("cvt.rna.tf32.f32 %0, %1;" : "=r"(u) : "f"(f));
    return __uint_as_float(u);
}
__device__ __forceinline__ void mma_tf32(float* d, const uint32_t* a, const uint32_t* b) {
    asm volatile(
        "mma.sync.aligned.m16n8k8.row.col.f32.tf32.tf32.f32 "
        "{%0,%1,%2,%3}, {%4,%5,%6,%7}, {%8,%9}, {%0,%1,%2,%3};"
        : "+f"(d[0]), "+f"(d[1]), "+f"(d[2]), "+f"(d[3])
        : "r"(a[0]), "r"(a[1]), "r"(a[2]), "r"(a[3]), "r"(b[0]), "r"(b[1]));
}

// ---------------- tf32 pre-round pass (weights + x), float4-vectorized ----------------
static constexpr int N4_X    = MTOT * DM / 4;
static constexpr int N4_WIN  = 2 * EE * DM / 4;
static constexpr int N4_WSEL = SEL * EE / 4;
static constexpr int N4_DTW  = EE * RR / 4;
static constexpr int N4_WOUT = DM * EE / 4;
static constexpr int N4_TOT  = N4_X + N4_WIN + N4_WSEL + N4_DTW + N4_WOUT;

__global__ __launch_bounds__(256)
void round_tf32_kernel(const float4* __restrict__ x,   float4* __restrict__ xr,
                       const float4* __restrict__ win, float4* __restrict__ winr,
                       const float4* __restrict__ wsel, float4* __restrict__ wselr,
                       const float4* __restrict__ dtw, float4* __restrict__ dtwr,
                       const float4* __restrict__ wout, float4* __restrict__ woutr)
{
    int i = blockIdx.x * blockDim.x + threadIdx.x;
    if (i >= N4_TOT) return;
    const float4* src; float4* dst; int j = i;
    if (j < N4_X) { src = x; dst = xr; }
    else if ((j -= N4_X) < N4_WIN) { src = win; dst = winr; }
    else if ((j -= N4_WIN) < N4_WSEL) { src = wsel; dst = wselr; }
    else if ((j -= N4_WSEL) < N4_DTW) { src = dtw; dst = dtwr; }
    else { j -= N4_DTW; src = wout; dst = woutr; }
    float4 v = src[j];
    v.x = f2tf32(v.x); v.y = f2tf32(v.y); v.z = f2tf32(v.z); v.w = f2tf32(v.w);
    dst[j] = v;
}

// ================= tf32 tensor GEMM: C[M,N] = A[M,K] @ B[N,K]^T =================
// All operands are pre-rounded to tf32 -> raw loads feed mma directly (HW truncation
// of already-rounded values is identity). BK = 32. Double-buffered cp.async.
// EPI: 0 = none, 1 = softplus(x + bias[col]), 2 = round-to-tf32 if col < RR.
template<int BM, int BN, int WM, int WN, int EPI>
__global__ __launch_bounds__(256, 2)
void mma_gemm(const float* __restrict__ A, const float* __restrict__ Bw,
              float* __restrict__ C, int K, int lda, int ldb, int ldc,
              const float* __restrict__ bias)
{
    constexpr int WARPS_M = BM / WM;
    constexpr int MT = WM / 16;
    constexpr int NT = WN / 8;
    constexpr int BUF = (BM + BN) * 32;            // floats per stage
    static_assert((BM / WM) * (BN / WN) == 8, "8 warps");

    extern __shared__ float smem[];
    const uint32_t smem_b = smem_u32(smem);

    const int tid  = threadIdx.x;
    const int lane = tid & 31, wid = tid >> 5;
    const int wm = wid % WARPS_M, wn = wid / WARPS_M;
    const int qr = lane >> 2, kin = lane & 3;
    const int m0 = blockIdx.y * BM, n0 = blockIdx.x * BN;

    float acc[MT][NT][4];
#pragma unroll
    for (int i = 0; i < MT; i++)
#pragma unroll
        for (int j = 0; j < NT; j++)
#pragma unroll
            for (int q = 0; q < 4; q++) acc[i][j][q] = 0.f;

    auto load_chunk = [&](int kt, int buf) {
        const uint32_t ab = smem_b + buf * BUF * 4;
        const uint32_t bb = ab + BM * 128;
#pragma unroll
        for (int it = 0; it < BM * 8 / 256; it++) {
            int idx = tid + it * 256;
            int r = idx >> 3, c = idx & 7;
            cp_async16(ab + (uint32_t)(c * BM + (r ^ c)) * 16,
                       A + (size_t)(m0 + r) * lda + kt + c * 4);
        }
#pragma unroll
        for (int it = 0; it < BN * 8 / 256; it++) {
            int idx = tid + it * 256;
            int r = idx >> 3, c = idx & 7;
            cp_async16(bb + (uint32_t)(c * BN + (r ^ c)) * 16,
                       Bw + (size_t)(n0 + r) * ldb + kt + c * 4);
        }
        asm volatile("cp.async.commit_group;" ::: "memory");
    };

    const int nch = K / 32;
    load_chunk(0, 0);

    for (int i = 0; i < nch; i++) {
        if (i + 1 < nch) {
            load_chunk((i + 1) * 32, (i + 1) & 1);
            asm volatile("cp.async.wait_group 1;" ::: "memory");
        } else {
            asm volatile("cp.async.wait_group 0;" ::: "memory");
        }
        __syncthreads();

        const float* As = smem + (i & 1) * BUF;
        const float* Bs = As + BM * 32;
#pragma unroll
        for (int ks = 0; ks < 4; ks++) {
            const int k4a = ks * 2, k4b = k4a + 1;
            uint32_t af[MT][4], bf[NT][2];
#pragma unroll
            for (int t = 0; t < MT; t++) {
                const int mb = wm * WM + t * 16;
                af[t][0] = __float_as_uint(As[(k4a * BM + mb +     (qr ^ k4a)) * 4 + kin]);
                af[t][1] = __float_as_uint(As[(k4a * BM + mb + 8 + (qr ^ k4a)) * 4 + kin]);
                af[t][2] = __float_as_uint(As[(k4b * BM + mb +     (qr ^ k4b)) * 4 + kin]);
                af[t][3] = __float_as_uint(As[(k4b * BM + mb + 8 + (qr ^ k4b)) * 4 + kin]);
            }
#pragma unroll
            for (int j = 0; j < NT; j++) {
                const int nb = wn * WN + j * 8;
                bf[j][0] = __float_as_uint(Bs[(k4a * BN + nb + (qr ^ k4a)) * 4 + kin]);
                bf[j][1] = __float_as_uint(Bs[(k4b * BN + nb + (qr ^ k4b)) * 4 + kin]);
            }
#pragma unroll
            for (int t = 0; t < MT; t++)
#pragma unroll
                for (int j = 0; j < NT; j++)
                    mma_tf32(acc[t][j], af[t], bf[j]);
        }
        __syncthreads();
    }

    // ---------------- epilogue ----------------
#pragma unroll
    for (int t = 0; t < MT; t++) {
#pragma unroll
        for (int j = 0; j < NT; j++) {
            const int row = m0 + wm * WM + t * 16 + qr;
            const int col = n0 + wn * WN + j * 8 + kin * 2;
            float v0 = acc[t][j][0], v1 = acc[t][j][1];
            float v2 = acc[t][j][2], v3 = acc[t][j][3];
            if (EPI == 1) {
                const float b0 = bias[col], b1 = bias[col + 1];
                float x0 = v0 + b0, x1 = v1 + b1, x2 = v2 + b0, x3 = v3 + b1;
                v0 = (x0 > 20.f) ? x0 : log1pf(__expf(x0));
                v1 = (x1 > 20.f) ? x1 : log1pf(__expf(x1));
                v2 = (x2 > 20.f) ? x2 : log1pf(__expf(x2));
                v3 = (x3 > 20.f) ? x3 : log1pf(__expf(x3));
            }
            if (EPI == 2 && col < RR) {   // dt_low columns feed GEMM4 as tf32
                v0 = f2tf32(v0); v1 = f2tf32(v1); v2 = f2tf32(v2); v3 = f2tf32(v3);
            }
            *reinterpret_cast<float2*>(C + (size_t)row * ldc + col)       = make_float2(v0, v1);
            *reinterpret_cast<float2*>(C + (size_t)(row + 8) * ldc + col) = make_float2(v2, v3);
        }
    }
}

// ---------------- causal depthwise conv1d (K=3) + bias + SiLU ----------------
__global__ __launch_bounds__(256)
void conv_silu_kernel(const float* __restrict__ xz,
                      const float* __restrict__ cw,
                      const float* __restrict__ cb,
                      float* __restrict__ u,
                      float* __restrict__ ur)
{
    int idx = blockIdx.x * blockDim.x + threadIdx.x;   // over B*L*E = 8.4M
    int e = idx % EE;
    int bt = idx / EE;          // b*L + t
    int t = bt % LEN;
    const float* xc = xz + (size_t)(bt - t) * (2 * EE);  // start of (b, 0) row

    float acc = cb[e];
    float w0 = cw[e * 3 + 0], w1 = cw[e * 3 + 1], w2 = cw[e * 3 + 2];
    if (t >= 2) acc = fmaf(w0, xc[(size_t)(t - 2) * (2 * EE) + e], acc);
    if (t >= 1) acc = fmaf(w1, xc[(size_t)(t - 1) * (2 * EE) + e], acc);
    acc = fmaf(w2, xc[(size_t)t * (2 * EE) + e], acc);
    float s = acc / (1.f + __expf(-acc));   // silu
    u[idx]  = s;                            // full precision (scan)
    ur[idx] = f2tf32(s);                    // tf32-rounded (GEMM3 operand)
}

// ---------------- selective scan (16 lanes per channel, state-per-lane) ----------------
__global__ __launch_bounds__(256)
void scan_kernel(const float* __restrict__ delta,
                 const float* __restrict__ u,
                 const float* __restrict__ dbc,
                 const float* __restrict__ xz,
                 const float* __restrict__ A_log,
                 const float* __restrict__ D_param,
                 float* __restrict__ yout)
{
    const int gid = blockIdx.x * (blockDim.x >> 4) + (threadIdx.x >> 4); // channel (b*E+e)
    const int n   = threadIdx.x & 15;
    const int b   = gid / EE;
    const int e   = gid % EE;

    const float An = -__expf(A_log[e * NN + n]);
    const float Dp = D_param[e];

    const float* dptr = delta + (size_t)b * LEN * EE + e;
    const float* uptr = u     + (size_t)b * LEN * EE + e;
    const float* zptr = xz    + (size_t)b * LEN * (2 * EE) + EE + e;
    const float* bptr = dbc   + (size_t)b * LEN * SEL + RR + n;
    const float* cptr = bptr + NN;
    float*       yptr = yout  + (size_t)b * LEN * EE + e;

    float h = 0.f;
    float d_c = dptr[0], u_c = uptr[0], z_c = zptr[0], B_c = bptr[0], C_c = cptr[0];

    for (int t = 0; t < LEN; t++) {
        float d_n = 0.f, u_n = 0.f, z_n = 0.f, B_n = 0.f, C_n = 0.f;
        if (t + 1 < LEN) {
            d_n = dptr[(size_t)(t + 1) * EE];
            u_n = uptr[(size_t)(t + 1) * EE];
            z_n = zptr[(size_t)(t + 1) * (2 * EE)];
            B_n = bptr[(size_t)(t + 1) * SEL];
            C_n = cptr[(size_t)(t + 1) * SEL];
        }
        float dA = __expf(d_c * An);
        h = fmaf(dA, h, d_c * u_c * B_c);
        float p = h * C_c;
        p += __shfl_xor_sync(0xffffffffu, p, 1);
        p += __shfl_xor_sync(0xffffffffu, p, 2);
        p += __shfl_xor_sync(0xffffffffu, p, 4);
        p += __shfl_xor_sync(0xffffffffu, p, 8);
        if (n == 0) {
            float sz = z_c / (1.f + __expf(-z_c));              // silu(z)
            yptr[(size_t)t * EE] = f2tf32((p + u_c * Dp) * sz); // y (tf32, feeds GEMM6)
        }
        d_c = d_n; u_c = u_n; z_c = z_n; B_c = B_n; C_c = C_n;
    }
}

// ---------------- launch ----------------
extern "C" void kernel_launch(void* const* d_in, const int* in_sizes, int n_in,
                              void* d_out, int out_size)
{
    const float* x       = (const float*)d_in[0];
    const float* W_in    = (const float*)d_in[1];
    const float* conv_w  = (const float*)d_in[2];
    const float* conv_b  = (const float*)d_in[3];
    const float* W_sel   = (const float*)d_in[4];
    const float* dt_w    = (const float*)d_in[5];
    const float* dt_b    = (const float*)d_in[6];
    const float* A_log   = (const float*)d_in[7];
    const float* D_param = (const float*)d_in[8];
    const float* W_out   = (const float*)d_in[9];
    float* out = (float*)d_out;

    float *xz, *u, *ur, *dbc, *delta, *y;
    float *xr, *winr, *wselr, *dtwr, *woutr;
    cudaGetSymbolAddress((void**)&xz,    g_xz);
    cudaGetSymbolAddress((void**)&u,     g_u);
    cudaGetSymbolAddress((void**)&ur,    g_ur);
    cudaGetSymbolAddress((void**)&dbc,   g_dbc);
    cudaGetSymbolAddress((void**)&delta, g_delta);
    cudaGetSymbolAddress((void**)&y,     g_y);
    cudaGetSymbolAddress((void**)&xr,    g_xr);
    cudaGetSymbolAddress((void**)&winr,  g_winr);
    cudaGetSymbolAddress((void**)&wselr, g_wselr);
    cudaGetSymbolAddress((void**)&dtwr,  g_dtwr);
    cudaGetSymbolAddress((void**)&woutr, g_woutr);

    constexpr int SM_BIG   = 2 * (128 + 128) * 32 * 4;  // 65536
    constexpr int SM_SMALL = 2 * (32 + 96) * 32 * 4;    // 32768
    cudaFuncSetAttribute((const void*)mma_gemm<128, 128, 64, 32, 0>,
                         cudaFuncAttributeMaxDynamicSharedMemorySize, SM_BIG);
    cudaFuncSetAttribute((const void*)mma_gemm<128, 128, 64, 32, 1>,
                         cudaFuncAttributeMaxDynamicSharedMemorySize, SM_BIG);
    cudaFuncSetAttribute((const void*)mma_gemm<32, 96, 16, 24, 2>,
                         cudaFuncAttributeMaxDynamicSharedMemorySize, SM_SMALL);

    // 0) pre-round all static GEMM operands to tf32
    round_tf32_kernel<<<(N4_TOT + 255) / 256, 256>>>(
        (const float4*)x, (float4*)xr, (const float4*)W_in, (float4*)winr,
        (const float4*)W_sel, (float4*)wselr, (const float4*)dt_w, (float4*)dtwr,
        (const float4*)W_out, (float4*)woutr);

    // 1) xz = x @ W_in^T   [4096, 4096], K=1024
    mma_gemm<128, 128, 64, 32, 0><<<dim3((2 * EE) / 128, MTOT / 128), 256, SM_BIG>>>(
        xr, winr, xz, DM, DM, DM, 2 * EE, nullptr);

    // 2) u = silu(causal_dwconv(xc) + b)   (writes full + tf32-rounded copies)
    conv_silu_kernel<<<(MTOT * EE) / 256, 256>>>(xz, conv_w, conv_b, u, ur);

    // 3) dbc = u @ W_sel^T   [4096, 96], K=2048  (dt_low cols rounded in epilogue)
    mma_gemm<32, 96, 16, 24, 2><<<dim3(1, MTOT / 32), 256, SM_SMALL>>>(
        ur, wselr, dbc, EE, EE, EE, SEL, nullptr);

    // 4) delta = softplus(dt_low @ dt_w^T + dt_b)   [4096, 2048], K=64, lda=96
    mma_gemm<128, 128, 64, 32, 1><<<dim3(EE / 128, MTOT / 128), 256, SM_BIG>>>(
        dbc, dtwr, delta, RR, SEL, RR, EE, dt_b);

    // 5) selective scan + D-skip + z-gating -> y (tf32-rounded)
    scan_kernel<<<(BSZ * EE) / 16, 256>>>(delta, u, dbc, xz, A_log, D_param, y);

    // 6) out = y @ W_out^T   [4096, 1024], K=2048
    mma_gemm<128, 128, 64, 32, 0><<<dim3(DM / 128, MTOT / 128), 256, SM_BIG>>>(
        y, woutr, out, EE, EE, EE, DM, nullptr);
}

// round 5
// speedup vs baseline: 1.1863x; 1.1863x over previous
#include <cuda_runtime.h>
#include <cuda_fp16.h>
#include <cstdint>

// Problem constants (ClassicMambaBlock: B=2, L=2048, Dm=1024, E=2048, N=16, R=64, K=3)
static constexpr int BSZ  = 2;
static constexpr int LEN  = 2048;
static constexpr int DM   = 1024;
static constexpr int EE   = 2048;
static constexpr int NN   = 16;
static constexpr int RR   = 64;
static constexpr int SEL  = RR + 2 * NN;   // 96
static constexpr int MTOT = BSZ * LEN;     // 4096

// ---------------- scratch (no cudaMalloc allowed) ----------------
__device__ float  g_xz[MTOT * 2 * EE];     // [M,4096]: cols [0,E)=xc, [E,2E)=z (fp32)
__device__ float  g_u[MTOT * EE];          // conv+silu (fp32, scan input)
__device__ float  g_dbc[MTOT * SEL];       // [M,96]: dt_low | B | C (fp32, scan reads B,C)
__device__ float  g_delta[MTOT * EE];      // softplus(dt) (fp32, scan input)
// fp16 GEMM operands
__device__ __half g_xh[MTOT * DM];
__device__ __half g_winh[2 * EE * DM];
__device__ __half g_wselh[SEL * EE];
__device__ __half g_dtwh[EE * RR];
__device__ __half g_wouth[DM * EE];
__device__ __half g_uh[MTOT * EE];         // conv output (GEMM3 A)
__device__ __half g_dtlh[MTOT * RR];       // dt_low (GEMM4 A), lda=64
__device__ __half g_yh[MTOT * EE];         // scan output (GEMM6 A)

// ================= helpers =================
__device__ __forceinline__ uint32_t smem_u32(const void* p) {
    uint32_t a;
    asm("{ .reg .u64 t; cvta.to.shared.u64 t, %1; cvt.u32.u64 %0, t; }" : "=r"(a) : "l"(p));
    return a;
}
__device__ __forceinline__ void cp_async16(uint32_t dst, const void* src) {
    asm volatile("cp.async.cg.shared.global [%0], [%1], 16;" :: "r"(dst), "l"(src));
}
__device__ __forceinline__ void mma_f16(float* d, const uint32_t* a, const uint32_t* b) {
    asm volatile(
        "mma.sync.aligned.m16n8k16.row.col.f32.f16.f16.f32 "
        "{%0,%1,%2,%3}, {%4,%5,%6,%7}, {%8,%9}, {%0,%1,%2,%3};"
        : "+f"(d[0]), "+f"(d[1]), "+f"(d[2]), "+f"(d[3])
        : "r"(a[0]), "r"(a[1]), "r"(a[2]), "r"(a[3]), "r"(b[0]), "r"(b[1]));
}

// ---------------- fp32 -> fp16 convert pass (x + all weights) ----------------
static constexpr int C4_X    = MTOT * DM / 4;
static constexpr int C4_WIN  = 2 * EE * DM / 4;
static constexpr int C4_WSEL = SEL * EE / 4;
static constexpr int C4_DTW  = EE * RR / 4;
static constexpr int C4_WOUT = DM * EE / 4;
static constexpr int C4_TOT  = C4_X + C4_WIN + C4_WSEL + C4_DTW + C4_WOUT;

__global__ __launch_bounds__(256)
void to_half_kernel(const float4* __restrict__ x,    __half* __restrict__ xh,
                    const float4* __restrict__ win,  __half* __restrict__ winh,
                    const float4* __restrict__ wsel, __half* __restrict__ wselh,
                    const float4* __restrict__ dtw,  __half* __restrict__ dtwh,
                    const float4* __restrict__ wout, __half* __restrict__ wouth)
{
    int i = blockIdx.x * blockDim.x + threadIdx.x;
    if (i >= C4_TOT) return;
    const float4* src; __half* dst; int j = i;
    if (j < C4_X) { src = x; dst = xh; }
    else if ((j -= C4_X) < C4_WIN) { src = win; dst = winh; }
    else if ((j -= C4_WIN) < C4_WSEL) { src = wsel; dst = wselh; }
    else if ((j -= C4_WSEL) < C4_DTW) { src = dtw; dst = dtwh; }
    else { j -= C4_DTW; src = wout; dst = wouth; }
    float4 v = src[j];
    __half2 h01 = __floats2half2_rn(v.x, v.y);
    __half2 h23 = __floats2half2_rn(v.z, v.w);
    uint2 pk = make_uint2(*reinterpret_cast<uint32_t*>(&h01), *reinterpret_cast<uint32_t*>(&h23));
    reinterpret_cast<uint2*>(dst)[j] = pk;
}

// ================= fp16 tensor GEMM: C[M,N] = A[M,K] @ B[N,K]^T, fp32 accum =============
// BK = 64 fp16 (128B rows). smem layout per operand: 16B unit at (c*ROWS + (r ^ c))*16,
// c = k/8 in [0,8). Conflict-free for cp.async stores and all fragment LDS.
// STAGES-deep cp.async pipeline. EPI: 0=none, 1=softplus(x+bias), 2=also write fp16
// copy of cols < RR into Ch (lda RR).
template<int BM, int BN, int WM, int WN, int STAGES, int EPI, int MINCTA>
__global__ __launch_bounds__(256, MINCTA)
void mma_gemm(const __half* __restrict__ A, const __half* __restrict__ Bw,
              float* __restrict__ C, int K, int lda, int ldb, int ldc,
              const float* __restrict__ bias, __half* __restrict__ Ch)
{
    constexpr int WARPS_M = BM / WM;
    constexpr int MT = WM / 16;
    constexpr int NT = WN / 8;
    constexpr int STAGE_B = (BM + BN) * 128;       // bytes per stage
    static_assert((BM / WM) * (BN / WN) == 8, "8 warps");

    extern __shared__ char smem[];
    const uint32_t smem_b = smem_u32(smem);

    const int tid  = threadIdx.x;
    const int lane = tid & 31, wid = tid >> 5;
    const int wm = wid % WARPS_M, wn = wid / WARPS_M;
    const int qr = lane >> 2, kin = lane & 3;
    const int m0 = blockIdx.y * BM, n0 = blockIdx.x * BN;

    float acc[MT][NT][4];
#pragma unroll
    for (int i = 0; i < MT; i++)
#pragma unroll
        for (int j = 0; j < NT; j++)
#pragma unroll
            for (int q = 0; q < 4; q++) acc[i][j][q] = 0.f;

    auto load_chunk = [&](int ck, int slot) {
        const int kt = ck * 64;
        const uint32_t ab = smem_b + slot * STAGE_B;
        const uint32_t bb = ab + BM * 128;
#pragma unroll
        for (int it = 0; it < BM * 8 / 256; it++) {
            int idx = tid + it * 256;
            int r = idx >> 3, c = idx & 7;
            cp_async16(ab + (uint32_t)(c * BM + (r ^ c)) * 16,
                       A + (size_t)(m0 + r) * lda + kt + c * 8);
        }
#pragma unroll
        for (int it = 0; it < BN * 8 / 256; it++) {
            int idx = tid + it * 256;
            int r = idx >> 3, c = idx & 7;
            cp_async16(bb + (uint32_t)(c * BN + (r ^ c)) * 16,
                       Bw + (size_t)(n0 + r) * ldb + kt + c * 8);
        }
        asm volatile("cp.async.commit_group;" ::: "memory");
    };

    const int nch = K / 64;
#pragma unroll
    for (int s = 0; s < STAGES - 1; s++)
        if (s < nch) load_chunk(s, s);

    for (int i = 0; i < nch; i++) {
        int w = nch - 1 - i;
        if (w > STAGES - 2) w = STAGES - 2;
        if (w == 0)      asm volatile("cp.async.wait_group 0;" ::: "memory");
        else             asm volatile("cp.async.wait_group 1;" ::: "memory");
        __syncthreads();

        const uint32_t* S = reinterpret_cast<const uint32_t*>(smem + (i % STAGES) * STAGE_B);
        const uint32_t* A32 = S;
        const uint32_t* B32 = S + BM * 32;
#pragma unroll
        for (int ks = 0; ks < 4; ks++) {
            const int cl = 2 * ks, chh = cl + 1;
            uint32_t af[MT][4], bf[NT][2];
#pragma unroll
            for (int t = 0; t < MT; t++) {
                const int ra = wm * WM + t * 16 + qr;
                af[t][0] = A32[(cl  * BM + (ra       ^ cl )) * 4 + kin];
                af[t][1] = A32[(cl  * BM + ((ra + 8) ^ cl )) * 4 + kin];
                af[t][2] = A32[(chh * BM + (ra       ^ chh)) * 4 + kin];
                af[t][3] = A32[(chh * BM + ((ra + 8) ^ chh)) * 4 + kin];
            }
#pragma unroll
            for (int j = 0; j < NT; j++) {
                const int rb = wn * WN + j * 8 + qr;
                bf[j][0] = B32[(cl  * BN + (rb ^ cl )) * 4 + kin];
                bf[j][1] = B32[(chh * BN + (rb ^ chh)) * 4 + kin];
            }
#pragma unroll
            for (int t = 0; t < MT; t++)
#pragma unroll
                for (int j = 0; j < NT; j++)
                    mma_f16(acc[t][j], af[t], bf[j]);
        }
        __syncthreads();

        const int pre = i + STAGES - 1;
        if (pre < nch) load_chunk(pre, pre % STAGES);
    }

    // ---------------- epilogue ----------------
#pragma unroll
    for (int t = 0; t < MT; t++) {
#pragma unroll
        for (int j = 0; j < NT; j++) {
            const int row = m0 + wm * WM + t * 16 + qr;
            const int col = n0 + wn * WN + j * 8 + kin * 2;
            float v0 = acc[t][j][0], v1 = acc[t][j][1];
            float v2 = acc[t][j][2], v3 = acc[t][j][3];
            if (EPI == 1) {
                const float b0 = bias[col], b1 = bias[col + 1];
                float x0 = v0 + b0, x1 = v1 + b1, x2 = v2 + b0, x3 = v3 + b1;
                v0 = (x0 > 20.f) ? x0 : log1pf(__expf(x0));
                v1 = (x1 > 20.f) ? x1 : log1pf(__expf(x1));
                v2 = (x2 > 20.f) ? x2 : log1pf(__expf(x2));
                v3 = (x3 > 20.f) ? x3 : log1pf(__expf(x3));
            }
            *reinterpret_cast<float2*>(C + (size_t)row * ldc + col)       = make_float2(v0, v1);
            *reinterpret_cast<float2*>(C + (size_t)(row + 8) * ldc + col) = make_float2(v2, v3);
            if (EPI == 2 && col < RR) {   // dt_low also as fp16 for the delta GEMM
                *reinterpret_cast<__half2*>(Ch + (size_t)row * RR + col)
                    = __floats2half2_rn(v0, v1);
                *reinterpret_cast<__half2*>(Ch + (size_t)(row + 8) * RR + col)
                    = __floats2half2_rn(v2, v3);
            }
        }
    }
}

// ---------------- causal depthwise conv1d (K=3) + bias + SiLU ----------------
__global__ __launch_bounds__(256)
void conv_silu_kernel(const float* __restrict__ xz,
                      const float* __restrict__ cw,
                      const float* __restrict__ cb,
                      float* __restrict__ u,
                      __half* __restrict__ uh)
{
    int idx = blockIdx.x * blockDim.x + threadIdx.x;   // over B*L*E = 8.4M
    int e = idx % EE;
    int bt = idx / EE;          // b*L + t
    int t = bt % LEN;
    const float* xc = xz + (size_t)(bt - t) * (2 * EE);  // start of (b, 0) row

    float acc = cb[e];
    float w0 = cw[e * 3 + 0], w1 = cw[e * 3 + 1], w2 = cw[e * 3 + 2];
    if (t >= 2) acc = fmaf(w0, xc[(size_t)(t - 2) * (2 * EE) + e], acc);
    if (t >= 1) acc = fmaf(w1, xc[(size_t)(t - 1) * (2 * EE) + e], acc);
    acc = fmaf(w2, xc[(size_t)t * (2 * EE) + e], acc);
    float s = acc / (1.f + __expf(-acc));   // silu
    u[idx]  = s;                 // fp32 for scan
    uh[idx] = __float2half_rn(s);// fp16 for GEMM3
}

// ---------------- selective scan (16 lanes per channel, state-per-lane) ----------------
__global__ __launch_bounds__(256)
void scan_kernel(const float* __restrict__ delta,
                 const float* __restrict__ u,
                 const float* __restrict__ dbc,
                 const float* __restrict__ xz,
                 const float* __restrict__ A_log,
                 const float* __restrict__ D_param,
                 __half* __restrict__ yout)
{
    const int gid = blockIdx.x * (blockDim.x >> 4) + (threadIdx.x >> 4); // channel (b*E+e)
    const int n   = threadIdx.x & 15;
    const int b   = gid / EE;
    const int e   = gid % EE;

    const float An = -__expf(A_log[e * NN + n]);
    const float Dp = D_param[e];

    const float* dptr = delta + (size_t)b * LEN * EE + e;
    const float* uptr = u     + (size_t)b * LEN * EE + e;
    const float* zptr = xz    + (size_t)b * LEN * (2 * EE) + EE + e;
    const float* bptr = dbc   + (size_t)b * LEN * SEL + RR + n;
    const float* cptr = bptr + NN;
    __half*      yptr = yout  + (size_t)b * LEN * EE + e;

    float h = 0.f;
    float d_c = dptr[0], u_c = uptr[0], z_c = zptr[0], B_c = bptr[0], C_c = cptr[0];

    for (int t = 0; t < LEN; t++) {
        float d_n = 0.f, u_n = 0.f, z_n = 0.f, B_n = 0.f, C_n = 0.f;
        if (t + 1 < LEN) {
            d_n = dptr[(size_t)(t + 1) * EE];
            u_n = uptr[(size_t)(t + 1) * EE];
            z_n = zptr[(size_t)(t + 1) * (2 * EE)];
            B_n = bptr[(size_t)(t + 1) * SEL];
            C_n = cptr[(size_t)(t + 1) * SEL];
        }
        float dA = __expf(d_c * An);
        h = fmaf(dA, h, d_c * u_c * B_c);
        float p = h * C_c;
        p += __shfl_xor_sync(0xffffffffu, p, 1);
        p += __shfl_xor_sync(0xffffffffu, p, 2);
        p += __shfl_xor_sync(0xffffffffu, p, 4);
        p += __shfl_xor_sync(0xffffffffu, p, 8);
        if (n == 0) {
            float sz = z_c / (1.f + __expf(-z_c));               // silu(z)
            yptr[(size_t)t * EE] = __float2half_rn((p + u_c * Dp) * sz);
        }
        d_c = d_n; u_c = u_n; z_c = z_n; B_c = B_n; C_c = C_n;
    }
}

// ---------------- launch ----------------
extern "C" void kernel_launch(void* const* d_in, const int* in_sizes, int n_in,
                              void* d_out, int out_size)
{
    const float* x       = (const float*)d_in[0];
    const float* W_in    = (const float*)d_in[1];
    const float* conv_w  = (const float*)d_in[2];
    const float* conv_b  = (const float*)d_in[3];
    const float* W_sel   = (const float*)d_in[4];
    const float* dt_w    = (const float*)d_in[5];
    const float* dt_b    = (const float*)d_in[6];
    const float* A_log   = (const float*)d_in[7];
    const float* D_param = (const float*)d_in[8];
    const float* W_out   = (const float*)d_in[9];
    float* out = (float*)d_out;

    float *xz, *u, *dbc, *delta;
    __half *xh, *winh, *wselh, *dtwh, *wouth, *uh, *dtlh, *yh;
    cudaGetSymbolAddress((void**)&xz,    g_xz);
    cudaGetSymbolAddress((void**)&u,     g_u);
    cudaGetSymbolAddress((void**)&dbc,   g_dbc);
    cudaGetSymbolAddress((void**)&delta, g_delta);
    cudaGetSymbolAddress((void**)&xh,    g_xh);
    cudaGetSymbolAddress((void**)&winh,  g_winh);
    cudaGetSymbolAddress((void**)&wselh, g_wselh);
    cudaGetSymbolAddress((void**)&dtwh,  g_dtwh);
    cudaGetSymbolAddress((void**)&wouth, g_wouth);
    cudaGetSymbolAddress((void**)&uh,    g_uh);
    cudaGetSymbolAddress((void**)&dtlh,  g_dtlh);
    cudaGetSymbolAddress((void**)&yh,    g_yh);

    constexpr int SM_BIG   = 3 * (128 + 128) * 128;  // 98304
    constexpr int SM_SMALL = 3 * (32 + 96) * 128;    // 49152
    cudaFuncSetAttribute((const void*)mma_gemm<128, 128, 64, 32, 3, 0, 2>,
                         cudaFuncAttributeMaxDynamicSharedMemorySize, SM_BIG);
    cudaFuncSetAttribute((const void*)mma_gemm<128, 128, 64, 32, 3, 1, 2>,
                         cudaFuncAttributeMaxDynamicSharedMemorySize, SM_BIG);
    cudaFuncSetAttribute((const void*)mma_gemm<32, 96, 16, 24, 3, 2, 2>,
                         cudaFuncAttributeMaxDynamicSharedMemorySize, SM_SMALL);

    // 0) convert x + weights to fp16
    to_half_kernel<<<(C4_TOT + 255) / 256, 256>>>(
        (const float4*)x, xh, (const float4*)W_in, winh,
        (const float4*)W_sel, wselh, (const float4*)dt_w, dtwh,
        (const float4*)W_out, wouth);

    // 1) xz = x @ W_in^T   [4096, 4096], K=1024
    mma_gemm<128, 128, 64, 32, 3, 0, 2><<<dim3((2 * EE) / 128, MTOT / 128), 256, SM_BIG>>>(
        xh, winh, xz, DM, DM, DM, 2 * EE, nullptr, nullptr);

    // 2) u = silu(causal_dwconv(xc) + b)   (fp32 + fp16 copies)
    conv_silu_kernel<<<(MTOT * EE) / 256, 256>>>(xz, conv_w, conv_b, u, uh);

    // 3) dbc = u @ W_sel^T   [4096, 96], K=2048  (dt_low also as fp16)
    mma_gemm<32, 96, 16, 24, 3, 2, 2><<<dim3(1, MTOT / 32), 256, SM_SMALL>>>(
        uh, wselh, dbc, EE, EE, EE, SEL, nullptr, dtlh);

    // 4) delta = softplus(dt_low @ dt_w^T + dt_b)   [4096, 2048], K=64
    mma_gemm<128, 128, 64, 32, 3, 1, 2><<<dim3(EE / 128, MTOT / 128), 256, SM_BIG>>>(
        dtlh, dtwh, delta, RR, RR, RR, EE, dt_b, nullptr);

    // 5) selective scan + D-skip + z-gating -> y (fp16)
    scan_kernel<<<(BSZ * EE) / 16, 256>>>(delta, u, dbc, xz, A_log, D_param, yh);

    // 6) out = y @ W_out^T   [4096, 1024], K=2048
    mma_gemm<128, 128, 64, 32, 3, 0, 2><<<dim3(DM / 128, MTOT / 128), 256, SM_BIG>>>(
        yh, wouth, out, EE, EE, EE, DM, nullptr, nullptr);
}

// round 6
// speedup vs baseline: 1.4399x; 1.2138x over previous
#include <cuda_runtime.h>
#include <cuda_fp16.h>
#include <cstdint>

// Problem constants (ClassicMambaBlock: B=2, L=2048, Dm=1024, E=2048, N=16, R=64, K=3)
static constexpr int BSZ  = 2;
static constexpr int LEN  = 2048;
static constexpr int DM   = 1024;
static constexpr int EE   = 2048;
static constexpr int NN   = 16;
static constexpr int RR   = 64;
static constexpr int SEL  = RR + 2 * NN;   // 96
static constexpr int SELP = 128;           // padded to 128 for GEMM3 tiling
static constexpr int MTOT = BSZ * LEN;     // 4096

// ---------------- scratch (no cudaMalloc allowed) ----------------
__device__ float  g_xz[MTOT * 2 * EE];     // [M,4096]: cols [0,E)=xc, [E,2E)=z (fp32)
__device__ float  g_u[MTOT * EE];          // conv+silu (fp32, scan input)
__device__ float  g_dbc[MTOT * SEL];       // [M,96]: dt_low | B | C (fp32, scan reads B,C)
__device__ float  g_delta[MTOT * EE];      // softplus(dt) (fp32, scan input)
// fp16 GEMM operands
__device__ __half g_xh[MTOT * DM];
__device__ __half g_winh[2 * EE * DM];
__device__ __half g_wselh[SELP * EE];      // rows 96..127 zero-padded
__device__ __half g_dtwh[EE * RR];
__device__ __half g_wouth[DM * EE];
__device__ __half g_uh[MTOT * EE];         // conv output (GEMM3 A)
__device__ __half g_dtlh[MTOT * RR];       // dt_low (GEMM4 A), lda=64
__device__ __half g_yh[MTOT * EE];         // scan output (GEMM6 A)

// ================= helpers =================
__device__ __forceinline__ uint32_t smem_u32(const void* p) {
    uint32_t a;
    asm("{ .reg .u64 t; cvta.to.shared.u64 t, %1; cvt.u32.u64 %0, t; }" : "=r"(a) : "l"(p));
    return a;
}
__device__ __forceinline__ void cp_async16(uint32_t dst, const void* src) {
    asm volatile("cp.async.cg.shared.global [%0], [%1], 16;" :: "r"(dst), "l"(src));
}
__device__ __forceinline__ void ldm_x4(uint32_t* r, uint32_t addr) {
    asm volatile("ldmatrix.sync.aligned.m8n8.x4.shared.b16 {%0,%1,%2,%3}, [%4];"
                 : "=r"(r[0]), "=r"(r[1]), "=r"(r[2]), "=r"(r[3]) : "r"(addr));
}
__device__ __forceinline__ void mma_f16(float* d, const uint32_t* a, const uint32_t* b) {
    asm volatile(
        "mma.sync.aligned.m16n8k16.row.col.f32.f16.f16.f32 "
        "{%0,%1,%2,%3}, {%4,%5,%6,%7}, {%8,%9}, {%0,%1,%2,%3};"
        : "+f"(d[0]), "+f"(d[1]), "+f"(d[2]), "+f"(d[3])
        : "r"(a[0]), "r"(a[1]), "r"(a[2]), "r"(a[3]), "r"(b[0]), "r"(b[1]));
}

// ---------------- fp32 -> fp16 convert pass (x + all weights) ----------------
static constexpr int C4_X    = MTOT * DM / 4;
static constexpr int C4_WIN  = 2 * EE * DM / 4;
static constexpr int C4_WSEL = SEL * EE / 4;
static constexpr int C4_DTW  = EE * RR / 4;
static constexpr int C4_WOUT = DM * EE / 4;
static constexpr int C4_PAD  = (SELP - SEL) * EE / 4;   // zero rows of wselh
static constexpr int C4_TOT  = C4_X + C4_WIN + C4_WSEL + C4_DTW + C4_WOUT + C4_PAD;

__global__ __launch_bounds__(256)
void to_half_kernel(const float4* __restrict__ x,    __half* __restrict__ xh,
                    const float4* __restrict__ win,  __half* __restrict__ winh,
                    const float4* __restrict__ wsel, __half* __restrict__ wselh,
                    const float4* __restrict__ dtw,  __half* __restrict__ dtwh,
                    const float4* __restrict__ wout, __half* __restrict__ wouth)
{
    int i = blockIdx.x * blockDim.x + threadIdx.x;
    if (i >= C4_TOT) return;
    const float4* src; __half* dst; int j = i;
    if (j < C4_X) { src = x; dst = xh; }
    else if ((j -= C4_X) < C4_WIN) { src = win; dst = winh; }
    else if ((j -= C4_WIN) < C4_WSEL) { src = wsel; dst = wselh; }
    else if ((j -= C4_WSEL) < C4_DTW) { src = dtw; dst = dtwh; }
    else if ((j -= C4_DTW) < C4_WOUT) { src = wout; dst = wouth; }
    else {  // zero padding rows 96..127 of wselh
        j -= C4_WOUT;
        reinterpret_cast<uint2*>(wselh + SEL * EE)[j] = make_uint2(0u, 0u);
        return;
    }
    float4 v = src[j];
    __half2 h01 = __floats2half2_rn(v.x, v.y);
    __half2 h23 = __floats2half2_rn(v.z, v.w);
    uint2 pk = make_uint2(*reinterpret_cast<uint32_t*>(&h01), *reinterpret_cast<uint32_t*>(&h23));
    reinterpret_cast<uint2*>(dst)[j] = pk;
}

// ================= fp16 tensor GEMM: C[M,N] = A[M,K] @ B[N,K]^T, fp32 accum =============
// BK = 64 fp16 (128B rows). smem: 16B unit at (c*ROWS + (r ^ c))*16, c = k/8 in [0,8).
// Conflict-free for cp.async stores and ldmatrix reads. ldmatrix.x4 fragment loads.
// STAGES-deep cp.async pipeline. Warp tile WM x WN (WM in {16,32}, WN multiple of 16).
// EPI: 0=none, 1=softplus(x+bias), 2=write C cols<SEL and fp16 copy of cols<RR into Ch.
template<int BM, int BN, int WM, int WN, int STAGES, int EPI>
__global__ __launch_bounds__((BM / WM) * (BN / WN) * 32)
void mma_gemm(const __half* __restrict__ A, const __half* __restrict__ Bw,
              float* __restrict__ C, int K, int lda, int ldb, int ldc,
              const float* __restrict__ bias, __half* __restrict__ Ch)
{
    constexpr int WARPS_M = BM / WM;
    constexpr int WARPS_N = BN / WN;
    constexpr int THREADS = WARPS_M * WARPS_N * 32;
    constexpr int MT = WM / 16;
    constexpr int NT = WN / 8;
    constexpr int STAGE_B = (BM + BN) * 128;       // bytes per stage
    static_assert(NT % 2 == 0, "NT even (paired ldmatrix)");

    extern __shared__ char smem[];
    const uint32_t smem_b = smem_u32(smem);

    const int tid  = threadIdx.x;
    const int lane = tid & 31, wid = tid >> 5;
    const int wm = wid % WARPS_M, wn = wid / WARPS_M;
    const int qr = lane >> 2, kin = lane & 3;
    const int m0 = blockIdx.y * BM, n0 = blockIdx.x * BN;
    const int lrow = lane & 15, lcof = lane >> 4;  // ldmatrix lane mapping

    float acc[MT][NT][4];
#pragma unroll
    for (int i = 0; i < MT; i++)
#pragma unroll
        for (int j = 0; j < NT; j++)
#pragma unroll
            for (int q = 0; q < 4; q++) acc[i][j][q] = 0.f;

    auto load_chunk = [&](int ck, int slot) {
        const int kt = ck * 64;
        const uint32_t ab = smem_b + slot * STAGE_B;
        const uint32_t bb = ab + BM * 128;
#pragma unroll
        for (int it = 0; it < BM * 8 / THREADS; it++) {
            int idx = tid + it * THREADS;
            int r = idx >> 3, c = idx & 7;
            cp_async16(ab + (uint32_t)(c * BM + (r ^ c)) * 16,
                       A + (size_t)(m0 + r) * lda + kt + c * 8);
        }
#pragma unroll
        for (int it = 0; it < BN * 8 / THREADS; it++) {
            int idx = tid + it * THREADS;
            int r = idx >> 3, c = idx & 7;
            cp_async16(bb + (uint32_t)(c * BN + (r ^ c)) * 16,
                       Bw + (size_t)(n0 + r) * ldb + kt + c * 8);
        }
        asm volatile("cp.async.commit_group;" ::: "memory");
    };

    const int nch = K / 64;
#pragma unroll
    for (int s = 0; s < STAGES - 1; s++)
        if (s < nch) load_chunk(s, s);

    for (int i = 0; i < nch; i++) {
        int w = nch - 1 - i;
        if (w > STAGES - 2) w = STAGES - 2;
        if      (w <= 0) asm volatile("cp.async.wait_group 0;" ::: "memory");
        else if (w == 1) asm volatile("cp.async.wait_group 1;" ::: "memory");
        else if (w == 2) asm volatile("cp.async.wait_group 2;" ::: "memory");
        else if (w == 3) asm volatile("cp.async.wait_group 3;" ::: "memory");
        else             asm volatile("cp.async.wait_group 4;" ::: "memory");
        __syncthreads();

        const uint32_t sa = smem_b + (i % STAGES) * STAGE_B;
        const uint32_t sb = sa + BM * 128;
#pragma unroll
        for (int ks = 0; ks < 4; ks++) {
            const int c = 2 * ks + lcof;
            uint32_t af[MT][4], bf[NT][2];
#pragma unroll
            for (int t = 0; t < MT; t++) {
                const int row = wm * WM + t * 16 + lrow;
                ldm_x4(af[t], sa + (uint32_t)(c * BM + (row ^ c)) * 16);
            }
#pragma unroll
            for (int p = 0; p < NT / 2; p++) {
                const int row = wn * WN + p * 16 + lrow;
                uint32_t r4[4];
                ldm_x4(r4, sb + (uint32_t)(c * BN + (row ^ c)) * 16);
                bf[2 * p][0] = r4[0]; bf[2 * p + 1][0] = r4[1];
                bf[2 * p][1] = r4[2]; bf[2 * p + 1][1] = r4[3];
            }
#pragma unroll
            for (int t = 0; t < MT; t++)
#pragma unroll
                for (int j = 0; j < NT; j++)
                    mma_f16(acc[t][j], af[t], bf[j]);
        }
        __syncthreads();

        const int pre = i + STAGES - 1;
        if (pre < nch) load_chunk(pre, pre % STAGES);
    }

    // ---------------- epilogue ----------------
#pragma unroll
    for (int t = 0; t < MT; t++) {
#pragma unroll
        for (int j = 0; j < NT; j++) {
            const int row = m0 + wm * WM + t * 16 + qr;
            const int col = n0 + wn * WN + j * 8 + kin * 2;
            float v0 = acc[t][j][0], v1 = acc[t][j][1];
            float v2 = acc[t][j][2], v3 = acc[t][j][3];
            if (EPI == 1) {
                const float b0 = bias[col], b1 = bias[col + 1];
                float x0 = v0 + b0, x1 = v1 + b1, x2 = v2 + b0, x3 = v3 + b1;
                v0 = (x0 > 20.f) ? x0 : log1pf(__expf(x0));
                v1 = (x1 > 20.f) ? x1 : log1pf(__expf(x1));
                v2 = (x2 > 20.f) ? x2 : log1pf(__expf(x2));
                v3 = (x3 > 20.f) ? x3 : log1pf(__expf(x3));
            }
            if (EPI == 2) {
                if (col < SEL) {
                    *reinterpret_cast<float2*>(C + (size_t)row * ldc + col)       = make_float2(v0, v1);
                    *reinterpret_cast<float2*>(C + (size_t)(row + 8) * ldc + col) = make_float2(v2, v3);
                }
                if (col < RR) {
                    *reinterpret_cast<__half2*>(Ch + (size_t)row * RR + col)
                        = __floats2half2_rn(v0, v1);
                    *reinterpret_cast<__half2*>(Ch + (size_t)(row + 8) * RR + col)
                        = __floats2half2_rn(v2, v3);
                }
            } else {
                *reinterpret_cast<float2*>(C + (size_t)row * ldc + col)       = make_float2(v0, v1);
                *reinterpret_cast<float2*>(C + (size_t)(row + 8) * ldc + col) = make_float2(v2, v3);
            }
        }
    }
}

// ---------------- causal depthwise conv1d (K=3) + bias + SiLU ----------------
__global__ __launch_bounds__(256)
void conv_silu_kernel(const float* __restrict__ xz,
                      const float* __restrict__ cw,
                      const float* __restrict__ cb,
                      float* __restrict__ u,
                      __half* __restrict__ uh)
{
    int idx = blockIdx.x * blockDim.x + threadIdx.x;   // over B*L*E = 8.4M
    int e = idx % EE;
    int bt = idx / EE;          // b*L + t
    int t = bt % LEN;
    const float* xc = xz + (size_t)(bt - t) * (2 * EE);  // start of (b, 0) row

    float acc = cb[e];
    float w0 = cw[e * 3 + 0], w1 = cw[e * 3 + 1], w2 = cw[e * 3 + 2];
    if (t >= 2) acc = fmaf(w0, xc[(size_t)(t - 2) * (2 * EE) + e], acc);
    if (t >= 1) acc = fmaf(w1, xc[(size_t)(t - 1) * (2 * EE) + e], acc);
    acc = fmaf(w2, xc[(size_t)t * (2 * EE) + e], acc);
    float s = acc / (1.f + __expf(-acc));   // silu
    u[idx]  = s;                  // fp32 for scan
    uh[idx] = __float2half_rn(s); // fp16 for GEMM3
}

// ---------------- selective scan (16 lanes per channel, prefetch depth 2) ----------------
__global__ __launch_bounds__(256)
void scan_kernel(const float* __restrict__ delta,
                 const float* __restrict__ u,
                 const float* __restrict__ dbc,
                 const float* __restrict__ xz,
                 const float* __restrict__ A_log,
                 const float* __restrict__ D_param,
                 __half* __restrict__ yout)
{
    const int gid = blockIdx.x * (blockDim.x >> 4) + (threadIdx.x >> 4); // channel (b*E+e)
    const int n   = threadIdx.x & 15;
    const int b   = gid / EE;
    const int e   = gid % EE;

    const float An = -__expf(A_log[e * NN + n]);
    const float Dp = D_param[e];

    const float* dptr = delta + (size_t)b * LEN * EE + e;
    const float* uptr = u     + (size_t)b * LEN * EE + e;
    const float* zptr = xz    + (size_t)b * LEN * (2 * EE) + EE + e;
    const float* bptr = dbc   + (size_t)b * LEN * SEL + RR + n;
    const float* cptr = bptr + NN;
    __half*      yptr = yout  + (size_t)b * LEN * EE + e;

    float h = 0.f;
    // prefetch depth 2
    float dc = dptr[0], uc = uptr[0], zc = zptr[0], Bc = bptr[0], Cc = cptr[0];
    float dn = dptr[EE], un = uptr[EE], zn = zptr[2 * EE], Bn = bptr[SEL], Cn = cptr[SEL];

    for (int t = 0; t < LEN; t++) {
        float d2 = 0.f, u2 = 0.f, z2 = 0.f, B2 = 0.f, C2 = 0.f;
        if (t + 2 < LEN) {
            d2 = dptr[(size_t)(t + 2) * EE];
            u2 = uptr[(size_t)(t + 2) * EE];
            z2 = zptr[(size_t)(t + 2) * (2 * EE)];
            B2 = bptr[(size_t)(t + 2) * SEL];
            C2 = cptr[(size_t)(t + 2) * SEL];
        }
        float dA = __expf(dc * An);
        h = fmaf(dA, h, dc * uc * Bc);
        float p = h * Cc;
        p += __shfl_xor_sync(0xffffffffu, p, 1);
        p += __shfl_xor_sync(0xffffffffu, p, 2);
        p += __shfl_xor_sync(0xffffffffu, p, 4);
        p += __shfl_xor_sync(0xffffffffu, p, 8);
        if (n == 0) {
            float sz = zc / (1.f + __expf(-zc));               // silu(z)
            yptr[(size_t)t * EE] = __float2half_rn((p + uc * Dp) * sz);
        }
        dc = dn; uc = un; zc = zn; Bc = Bn; Cc = Cn;
        dn = d2; un = u2; zn = z2; Bn = B2; Cn = C2;
    }
}

// ---------------- launch ----------------
extern "C" void kernel_launch(void* const* d_in, const int* in_sizes, int n_in,
                              void* d_out, int out_size)
{
    const float* x       = (const float*)d_in[0];
    const float* W_in    = (const float*)d_in[1];
    const float* conv_w  = (const float*)d_in[2];
    const float* conv_b  = (const float*)d_in[3];
    const float* W_sel   = (const float*)d_in[4];
    const float* dt_w    = (const float*)d_in[5];
    const float* dt_b    = (const float*)d_in[6];
    const float* A_log   = (const float*)d_in[7];
    const float* D_param = (const float*)d_in[8];
    const float* W_out   = (const float*)d_in[9];
    float* out = (float*)d_out;

    float *xz, *u, *dbc, *delta;
    __half *xh, *winh, *wselh, *dtwh, *wouth, *uh, *dtlh, *yh;
    cudaGetSymbolAddress((void**)&xz,    g_xz);
    cudaGetSymbolAddress((void**)&u,     g_u);
    cudaGetSymbolAddress((void**)&dbc,   g_dbc);
    cudaGetSymbolAddress((void**)&delta, g_delta);
    cudaGetSymbolAddress((void**)&xh,    g_xh);
    cudaGetSymbolAddress((void**)&winh,  g_winh);
    cudaGetSymbolAddress((void**)&wselh, g_wselh);
    cudaGetSymbolAddress((void**)&dtwh,  g_dtwh);
    cudaGetSymbolAddress((void**)&wouth, g_wouth);
    cudaGetSymbolAddress((void**)&uh,    g_uh);
    cudaGetSymbolAddress((void**)&dtlh,  g_dtlh);
    cudaGetSymbolAddress((void**)&yh,    g_yh);

    // kernel variants
    auto* k_big  = mma_gemm<128, 128, 32, 32, 4, 0>;   // 512 thr, 16 warps
    auto* k_dlt  = mma_gemm<128, 128, 32, 32, 2, 1>;   // K=64 -> 1 chunk
    auto* k_sel  = mma_gemm< 32, 128, 32, 16, 6, 2>;   // 256 thr, 8 warps

    constexpr int SM_BIG = 4 * (128 + 128) * 128;  // 131072
    constexpr int SM_DLT = 2 * (128 + 128) * 128;  // 65536
    constexpr int SM_SEL = 6 * ( 32 + 128) * 128;  // 122880
    cudaFuncSetAttribute((const void*)k_big, cudaFuncAttributeMaxDynamicSharedMemorySize, SM_BIG);
    cudaFuncSetAttribute((const void*)k_dlt, cudaFuncAttributeMaxDynamicSharedMemorySize, SM_DLT);
    cudaFuncSetAttribute((const void*)k_sel, cudaFuncAttributeMaxDynamicSharedMemorySize, SM_SEL);

    // 0) convert x + weights to fp16 (and zero-pad wselh rows 96..127)
    to_half_kernel<<<(C4_TOT + 255) / 256, 256>>>(
        (const float4*)x, xh, (const float4*)W_in, winh,
        (const float4*)W_sel, wselh, (const float4*)dt_w, dtwh,
        (const float4*)W_out, wouth);

    // 1) xz = x @ W_in^T   [4096, 4096], K=1024
    k_big<<<dim3((2 * EE) / 128, MTOT / 128), 512, SM_BIG>>>(
        xh, winh, xz, DM, DM, DM, 2 * EE, nullptr, nullptr);

    // 2) u = silu(causal_dwconv(xc) + b)   (fp32 + fp16 copies)
    conv_silu_kernel<<<(MTOT * EE) / 256, 256>>>(xz, conv_w, conv_b, u, uh);

    // 3) dbc = u @ W_sel^T   [4096, 96(pad 128)], K=2048
    k_sel<<<dim3(1, MTOT / 32), 256, SM_SEL>>>(
        uh, wselh, dbc, EE, EE, EE, SEL, nullptr, dtlh);

    // 4) delta = softplus(dt_low @ dt_w^T + dt_b)   [4096, 2048], K=64
    k_dlt<<<dim3(EE / 128, MTOT / 128), 512, SM_DLT>>>(
        dtlh, dtwh, delta, RR, RR, RR, EE, dt_b, nullptr);

    // 5) selective scan + D-skip + z-gating -> y (fp16)
    scan_kernel<<<(BSZ * EE) / 16, 256>>>(delta, u, dbc, xz, A_log, D_param, yh);

    // 6) out = y @ W_out^T   [4096, 1024], K=2048
    k_big<<<dim3(DM / 128, MTOT / 128), 512, SM_BIG>>>(
        yh, wouth, out, EE, EE, EE, DM, nullptr, nullptr);
}